// round 12
// baseline (speedup 1.0000x reference)
#include <cuda_runtime.h>

// LSTM: B=4096, T=512, I=10, H=32, O=1. Gate order i,f,g,o.
// R12: R2's exact schedule (recurrent weights in regs as PRE-SCALED f32x2
// j-pairs, even/odd-j halves accumulate in u64 halves, k-inner interleave,
// x-weights in smem, bias peeled into q=0 fma2) at NB=3 batches/warp:
// grid 1366 single-warp blocks <= 152 SMs x 9 = one wave at 2.25 warps/SMSP
// (+30% residency vs NB=4). launch_bounds(32,9) -> 227-reg cap; NB=3 demand
// ~210-225 so no spill cascade (R8's failure was the 204 cap at bound 10).

#define B_TOT 4096
#define T_LEN 512
#define I_DIM 10
#define H_DIM 32
#define NB 3
#define GRID_SZ ((B_TOT + NB - 1) / NB)   // 1366
#define XSTRIDE (T_LEN * I_DIM)           // 5120

#define S1 (-1.4426950408889634f)  // -log2(e): sigmoid gates i, f, o
#define S2 (-2.8853900817779268f)  // -2*log2(e): tanh gate g

typedef unsigned long long u64;

__device__ __forceinline__ u64 fma2(u64 a, u64 b, u64 c) {
    u64 d;
    asm("fma.rn.f32x2 %0, %1, %2, %3;" : "=l"(d) : "l"(a), "l"(b), "l"(c));
    return d;
}
__device__ __forceinline__ u64 pack2(float lo, float hi) {
    u64 d;
    asm("mov.b64 %0, {%1, %2};" : "=l"(d) : "f"(lo), "f"(hi));
    return d;
}
__device__ __forceinline__ void unpack2(u64 v, float& lo, float& hi) {
    asm("mov.b64 {%0, %1}, %2;" : "=f"(lo), "=f"(hi) : "l"(v));
}
__device__ __forceinline__ float ex2f(float x) {
    float y; asm("ex2.approx.f32 %0, %1;" : "=f"(y) : "f"(x)); return y;
}
__device__ __forceinline__ float rcpf(float x) {
    float y; asm("rcp.approx.f32 %0, %1;" : "=f"(y) : "f"(x)); return y;
}
// Pre-scaled activations: input already multiplied by S1 (sig) / S2 (tanh).
__device__ __forceinline__ float sig_pre(float y) {
    return rcpf(1.0f + ex2f(y));
}
__device__ __forceinline__ float tanh_pre(float y) {
    return fmaf(2.0f, rcpf(1.0f + ex2f(y)), -1.0f);
}
__device__ __forceinline__ float tanh_c(float x) {   // normal-domain tanh
    return fmaf(2.0f, rcpf(1.0f + ex2f(S2 * x)), -1.0f);
}

__global__ __launch_bounds__(32, 9) void lstm_r12_kernel(
    const float* __restrict__ x,    // [B, T, I]
    const float* __restrict__ Wih,  // [4H, I]
    const float* __restrict__ Whh,  // [4H, H]
    const float* __restrict__ bih,  // [4H]
    const float* __restrict__ bhh,  // [4H]
    const float* __restrict__ Wd,   // [1, H]
    const float* __restrict__ bd,   // [1]
    float* __restrict__ out)        // [B, 1]
{
    __shared__ ulonglong2 sWx_if[5][32];   // pre-scaled x-weights
    __shared__ ulonglong2 sWx_go[5][32];
    __shared__ __align__(16) float sH[NB][H_DIM];
    __shared__ __align__(16) float sX[NB][12];

    const int lane = threadIdx.x;
    const int b0 = blockIdx.x * NB;
    // Tail block (b0=4095): clamp load base; stores guarded at the end.
    const int b0c = (b0 + NB <= B_TOT) ? b0 : (B_TOT - NB);

    // ---- Recurrent weights into registers, PRE-SCALED (paired over j) ----
    u64 whi[16], whf[16], whg[16], who[16];
#pragma unroll
    for (int p = 0; p < 16; p++) {
        const float* r0 = &Whh[(0 * 32 + lane) * H_DIM + 2 * p];
        const float* r1 = &Whh[(1 * 32 + lane) * H_DIM + 2 * p];
        const float* r2 = &Whh[(2 * 32 + lane) * H_DIM + 2 * p];
        const float* r3 = &Whh[(3 * 32 + lane) * H_DIM + 2 * p];
        whi[p] = pack2(S1 * r0[0], S1 * r0[1]);
        whf[p] = pack2(S1 * r1[0], S1 * r1[1]);
        whg[p] = pack2(S2 * r2[0], S2 * r2[1]);
        who[p] = pack2(S1 * r3[0], S1 * r3[1]);
    }
    // x-weights into smem, pre-scaled, packed per gate-pair.
#pragma unroll
    for (int p = 0; p < 5; p++) {
        ulonglong2 v;
        v.x = pack2(S1 * Wih[(0 * 32 + lane) * I_DIM + 2 * p],
                    S1 * Wih[(0 * 32 + lane) * I_DIM + 2 * p + 1]);
        v.y = pack2(S1 * Wih[(1 * 32 + lane) * I_DIM + 2 * p],
                    S1 * Wih[(1 * 32 + lane) * I_DIM + 2 * p + 1]);
        sWx_if[p][lane] = v;
        v.x = pack2(S2 * Wih[(2 * 32 + lane) * I_DIM + 2 * p],
                    S2 * Wih[(2 * 32 + lane) * I_DIM + 2 * p + 1]);
        v.y = pack2(S1 * Wih[(3 * 32 + lane) * I_DIM + 2 * p],
                    S1 * Wih[(3 * 32 + lane) * I_DIM + 2 * p + 1]);
        sWx_go[p][lane] = v;
    }
    // Pre-scaled bias packed (bias, 0) for the q=0 peeled fma2.
    const u64 bp_i = pack2(S1 * (bih[0 * 32 + lane] + bhh[0 * 32 + lane]), 0.0f);
    const u64 bp_f = pack2(S1 * (bih[1 * 32 + lane] + bhh[1 * 32 + lane]), 0.0f);
    const u64 bp_g = pack2(S2 * (bih[2 * 32 + lane] + bhh[2 * 32 + lane]), 0.0f);
    const u64 bp_o = pack2(S1 * (bih[3 * 32 + lane] + bhh[3 * 32 + lane]), 0.0f);
    __syncwarp();

    float h[NB], c[NB], xv[NB];
#pragma unroll
    for (int k = 0; k < NB; k++) { h[k] = 0.0f; c[k] = 0.0f; xv[k] = 0.0f; }

    const float* xb = x + b0c * XSTRIDE + lane;
    if (lane < I_DIM) {
#pragma unroll
        for (int k = 0; k < NB; k++) xv[k] = xb[k * XSTRIDE];   // x(0)
    }
    int toff = I_DIM;   // element offset of x(t+1)

    for (int t = 0; t < T_LEN; t++) {
        // Publish compact h and x.
#pragma unroll
        for (int k = 0; k < NB; k++) sH[k][lane] = h[k];
        if (lane < I_DIM) {
#pragma unroll
            for (int k = 0; k < NB; k++) sX[k][lane] = xv[k];
        }
        __syncwarp();

        // Prefetch next timestep's x (clamped; overlaps gate compute).
        if (lane < I_DIM) {
#pragma unroll
            for (int k = 0; k < NB; k++) xv[k] = xb[k * XSTRIDE + toff];
        }
        toff = min(toff + I_DIM, XSTRIDE - I_DIM);

        u64 ai[NB], af[NB], ag[NB], ao[NB];
        // q = 0 peeled: bias enters via the fma2 addend (no init MOVs).
#pragma unroll
        for (int k = 0; k < NB; k++) {
            const ulonglong2 hp = *(const ulonglong2*)&sH[k][0];
            ai[k] = fma2(whi[0], hp.x, bp_i);
            af[k] = fma2(whf[0], hp.x, bp_f);
            ag[k] = fma2(whg[0], hp.x, bp_g);
            ao[k] = fma2(who[0], hp.x, bp_o);
            ai[k] = fma2(whi[1], hp.y, ai[k]);
            af[k] = fma2(whf[1], hp.y, af[k]);
            ag[k] = fma2(whg[1], hp.y, ag[k]);
            ao[k] = fma2(who[1], hp.y, ao[k]);
        }
#pragma unroll
        for (int q = 1; q < 8; q++) {
#pragma unroll
            for (int k = 0; k < NB; k++) {
                const ulonglong2 hp = *(const ulonglong2*)&sH[k][4 * q];
                ai[k] = fma2(whi[2 * q],     hp.x, ai[k]);
                af[k] = fma2(whf[2 * q],     hp.x, af[k]);
                ag[k] = fma2(whg[2 * q],     hp.x, ag[k]);
                ao[k] = fma2(who[2 * q],     hp.x, ao[k]);
                ai[k] = fma2(whi[2 * q + 1], hp.y, ai[k]);
                af[k] = fma2(whf[2 * q + 1], hp.y, af[k]);
                ag[k] = fma2(whg[2 * q + 1], hp.y, ag[k]);
                ao[k] = fma2(who[2 * q + 1], hp.y, ao[k]);
            }
        }
        // Input part: p-outer so only 4 weight u64s live at a time.
#pragma unroll
        for (int p = 0; p < 5; p++) {
            const ulonglong2 wif = sWx_if[p][lane];
            const ulonglong2 wgo = sWx_go[p][lane];
#pragma unroll
            for (int k = 0; k < NB; k++) {
                const u64 xq = *(const u64*)&sX[k][2 * p];
                ai[k] = fma2(wif.x, xq, ai[k]);
                af[k] = fma2(wif.y, xq, af[k]);
                ag[k] = fma2(wgo.x, xq, ag[k]);
                ao[k] = fma2(wgo.y, xq, ao[k]);
            }
        }

        // Activations (pre-scaled forms) + state update.
#pragma unroll
        for (int k = 0; k < NB; k++) {
            float lo, hi;
            unpack2(ai[k], lo, hi); const float gi = sig_pre(lo + hi);
            unpack2(af[k], lo, hi); const float gf = sig_pre(lo + hi);
            unpack2(ag[k], lo, hi); const float gg = tanh_pre(lo + hi);
            unpack2(ao[k], lo, hi); const float go = sig_pre(lo + hi);
            c[k] = fmaf(gf, c[k], gi * gg);
            h[k] = go * tanh_c(c[k]);
        }
        __syncwarp();
    }

    // Final dense: out[b] = sum_l h[b][l] * Wd[l] + bd (tail uses clamped b0c;
    // overlapping batches recompute identical values -> same stored result).
    const float wd = Wd[lane];
    const float bdv = bd[0];
#pragma unroll
    for (int k = 0; k < NB; k++) {
        float p = h[k] * wd;
#pragma unroll
        for (int off = 16; off; off >>= 1)
            p += __shfl_xor_sync(0xffffffffu, p, off);
        if (lane == 0) out[b0c + k] = p + bdv;
    }
}

extern "C" void kernel_launch(void* const* d_in, const int* in_sizes, int n_in,
                              void* d_out, int out_size) {
    const float* x   = (const float*)d_in[0];
    const float* Wih = (const float*)d_in[1];
    const float* Whh = (const float*)d_in[2];
    const float* bih = (const float*)d_in[3];
    const float* bhh = (const float*)d_in[4];
    const float* Wd  = (const float*)d_in[5];
    const float* bd  = (const float*)d_in[6];
    (void)in_sizes; (void)n_in; (void)out_size;

    lstm_r12_kernel<<<GRID_SZ, 32>>>(x, Wih, Whh, bih, bhh, Wd, bd,
                                     (float*)d_out);
}

// round 13
// speedup vs baseline: 1.5798x; 1.5798x over previous
#include <cuda_runtime.h>

// LSTM: B=4096, T=512, I=10, H=32, O=1. Gate order i,f,g,o.
// R13 = R2/R11 skeleton (NB=4 batches/warp, recurrent weights in regs as
// f32x2 j-pairs, even/odd-j halves in u64 halves, k-inner interleave,
// x-weights in smem, bias peeled into q=0 fma2, 1024 single-warp blocks)
// with MUFU.TANH activations:
//   sigmoid(x) = 0.5 + 0.5*tanh(x/2)  -> weights for i,f,o pre-scaled by 0.5
//   tanh(x)    = tanh.approx.f32 directly (g gate unscaled, tanh(c) direct)
// Cuts 20 MUFU ops/step and shortens every activation dependency chain.

#define B_TOT 4096
#define T_LEN 512
#define I_DIM 10
#define H_DIM 32
#define NB 4
#define XSTRIDE (T_LEN * I_DIM)   // 5120

#define SH (0.5f)   // pre-scale for sigmoid gates (i, f, o)

typedef unsigned long long u64;

__device__ __forceinline__ u64 fma2(u64 a, u64 b, u64 c) {
    u64 d;
    asm("fma.rn.f32x2 %0, %1, %2, %3;" : "=l"(d) : "l"(a), "l"(b), "l"(c));
    return d;
}
__device__ __forceinline__ u64 pack2(float lo, float hi) {
    u64 d;
    asm("mov.b64 %0, {%1, %2};" : "=l"(d) : "f"(lo), "f"(hi));
    return d;
}
__device__ __forceinline__ void unpack2(u64 v, float& lo, float& hi) {
    asm("mov.b64 {%0, %1}, %2;" : "=f"(lo), "=f"(hi) : "l"(v));
}
__device__ __forceinline__ float tanhm(float x) {
    float y; asm("tanh.approx.f32 %0, %1;" : "=f"(y) : "f"(x)); return y;
}
// Pre-scaled sigmoid: input already = x/2. sig(x) = 0.5 + 0.5*tanh(x/2).
__device__ __forceinline__ float sig_half(float y) {
    return fmaf(0.5f, tanhm(y), 0.5f);
}

__global__ __launch_bounds__(32, 8) void lstm_r13_kernel(
    const float* __restrict__ x,    // [B, T, I]
    const float* __restrict__ Wih,  // [4H, I]
    const float* __restrict__ Whh,  // [4H, H]
    const float* __restrict__ bih,  // [4H]
    const float* __restrict__ bhh,  // [4H]
    const float* __restrict__ Wd,   // [1, H]
    const float* __restrict__ bd,   // [1]
    float* __restrict__ out)        // [B, 1]
{
    __shared__ ulonglong2 sWx_if[5][32];   // pre-scaled x-weights
    __shared__ ulonglong2 sWx_go[5][32];
    __shared__ __align__(16) float sH[NB][H_DIM];
    __shared__ __align__(16) float sX[NB][12];

    const int lane = threadIdx.x;
    const int b0 = blockIdx.x * NB;

    // ---- Recurrent weights into registers (paired over j).
    // i,f,o rows scaled by 0.5 (sigmoid-via-tanh); g row unscaled.
    u64 whi[16], whf[16], whg[16], who[16];
#pragma unroll
    for (int p = 0; p < 16; p++) {
        const float* r0 = &Whh[(0 * 32 + lane) * H_DIM + 2 * p];
        const float* r1 = &Whh[(1 * 32 + lane) * H_DIM + 2 * p];
        const float* r2 = &Whh[(2 * 32 + lane) * H_DIM + 2 * p];
        const float* r3 = &Whh[(3 * 32 + lane) * H_DIM + 2 * p];
        whi[p] = pack2(SH * r0[0], SH * r0[1]);
        whf[p] = pack2(SH * r1[0], SH * r1[1]);
        whg[p] = pack2(r2[0], r2[1]);
        who[p] = pack2(SH * r3[0], SH * r3[1]);
    }
    // x-weights into smem, same scaling, packed per gate-pair.
#pragma unroll
    for (int p = 0; p < 5; p++) {
        ulonglong2 v;
        v.x = pack2(SH * Wih[(0 * 32 + lane) * I_DIM + 2 * p],
                    SH * Wih[(0 * 32 + lane) * I_DIM + 2 * p + 1]);
        v.y = pack2(SH * Wih[(1 * 32 + lane) * I_DIM + 2 * p],
                    SH * Wih[(1 * 32 + lane) * I_DIM + 2 * p + 1]);
        sWx_if[p][lane] = v;
        v.x = pack2(Wih[(2 * 32 + lane) * I_DIM + 2 * p],
                    Wih[(2 * 32 + lane) * I_DIM + 2 * p + 1]);
        v.y = pack2(SH * Wih[(3 * 32 + lane) * I_DIM + 2 * p],
                    SH * Wih[(3 * 32 + lane) * I_DIM + 2 * p + 1]);
        sWx_go[p][lane] = v;
    }
    // Scaled bias packed (bias, 0) for the q=0 peeled fma2.
    const u64 bp_i = pack2(SH * (bih[0 * 32 + lane] + bhh[0 * 32 + lane]), 0.0f);
    const u64 bp_f = pack2(SH * (bih[1 * 32 + lane] + bhh[1 * 32 + lane]), 0.0f);
    const u64 bp_g = pack2(bih[2 * 32 + lane] + bhh[2 * 32 + lane], 0.0f);
    const u64 bp_o = pack2(SH * (bih[3 * 32 + lane] + bhh[3 * 32 + lane]), 0.0f);
    __syncwarp();

    float h[NB], c[NB], xv[NB];
#pragma unroll
    for (int k = 0; k < NB; k++) { h[k] = 0.0f; c[k] = 0.0f; xv[k] = 0.0f; }

    const float* xb = x + b0 * XSTRIDE + lane;
    if (lane < I_DIM) {
#pragma unroll
        for (int k = 0; k < NB; k++) xv[k] = xb[k * XSTRIDE];   // x(0)
    }
    int toff = I_DIM;   // element offset of x(t+1)

    for (int t = 0; t < T_LEN; t++) {
        // Publish compact h and x.
#pragma unroll
        for (int k = 0; k < NB; k++) sH[k][lane] = h[k];
        if (lane < I_DIM) {
#pragma unroll
            for (int k = 0; k < NB; k++) sX[k][lane] = xv[k];
        }
        __syncwarp();

        // Prefetch next timestep's x (clamped; overlaps gate compute).
        if (lane < I_DIM) {
#pragma unroll
            for (int k = 0; k < NB; k++) xv[k] = xb[k * XSTRIDE + toff];
        }
        toff = min(toff + I_DIM, XSTRIDE - I_DIM);

        u64 ai[NB], af[NB], ag[NB], ao[NB];
        // q = 0 peeled: bias enters via the fma2 addend.
#pragma unroll
        for (int k = 0; k < NB; k++) {
            const ulonglong2 hp = *(const ulonglong2*)&sH[k][0];
            ai[k] = fma2(whi[0], hp.x, bp_i);
            af[k] = fma2(whf[0], hp.x, bp_f);
            ag[k] = fma2(whg[0], hp.x, bp_g);
            ao[k] = fma2(who[0], hp.x, bp_o);
            ai[k] = fma2(whi[1], hp.y, ai[k]);
            af[k] = fma2(whf[1], hp.y, af[k]);
            ag[k] = fma2(whg[1], hp.y, ag[k]);
            ao[k] = fma2(who[1], hp.y, ao[k]);
        }
#pragma unroll
        for (int q = 1; q < 8; q++) {
#pragma unroll
            for (int k = 0; k < NB; k++) {
                const ulonglong2 hp = *(const ulonglong2*)&sH[k][4 * q];
                ai[k] = fma2(whi[2 * q],     hp.x, ai[k]);
                af[k] = fma2(whf[2 * q],     hp.x, af[k]);
                ag[k] = fma2(whg[2 * q],     hp.x, ag[k]);
                ao[k] = fma2(who[2 * q],     hp.x, ao[k]);
                ai[k] = fma2(whi[2 * q + 1], hp.y, ai[k]);
                af[k] = fma2(whf[2 * q + 1], hp.y, af[k]);
                ag[k] = fma2(whg[2 * q + 1], hp.y, ag[k]);
                ao[k] = fma2(who[2 * q + 1], hp.y, ao[k]);
            }
        }
        // Input part: p-outer so only 4 weight u64s live at a time.
#pragma unroll
        for (int p = 0; p < 5; p++) {
            const ulonglong2 wif = sWx_if[p][lane];
            const ulonglong2 wgo = sWx_go[p][lane];
#pragma unroll
            for (int k = 0; k < NB; k++) {
                const u64 xq = *(const u64*)&sX[k][2 * p];
                ai[k] = fma2(wif.x, xq, ai[k]);
                af[k] = fma2(wif.y, xq, af[k]);
                ag[k] = fma2(wgo.x, xq, ag[k]);
                ao[k] = fma2(wgo.y, xq, ao[k]);
            }
        }

        // Activations via MUFU.TANH + state update.
#pragma unroll
        for (int k = 0; k < NB; k++) {
            float lo, hi;
            unpack2(ag[k], lo, hi); const float gg = tanhm(lo + hi);   // tanh
            unpack2(af[k], lo, hi); const float gf = sig_half(lo + hi);
            unpack2(ai[k], lo, hi); const float gi = sig_half(lo + hi);
            unpack2(ao[k], lo, hi); const float go = sig_half(lo + hi);
            c[k] = fmaf(gf, c[k], gi * gg);
            h[k] = go * tanhm(c[k]);
        }
        __syncwarp();
    }

    // Final dense: out[b] = sum_l h[b][l] * Wd[l] + bd
    const float wd = Wd[lane];
    const float bdv = bd[0];
#pragma unroll
    for (int k = 0; k < NB; k++) {
        float p = h[k] * wd;
#pragma unroll
        for (int off = 16; off; off >>= 1)
            p += __shfl_xor_sync(0xffffffffu, p, off);
        if (lane == 0) out[b0 + k] = p + bdv;
    }
}

extern "C" void kernel_launch(void* const* d_in, const int* in_sizes, int n_in,
                              void* d_out, int out_size) {
    const float* x   = (const float*)d_in[0];
    const float* Wih = (const float*)d_in[1];
    const float* Whh = (const float*)d_in[2];
    const float* bih = (const float*)d_in[3];
    const float* bhh = (const float*)d_in[4];
    const float* Wd  = (const float*)d_in[5];
    const float* bd  = (const float*)d_in[6];
    (void)in_sizes; (void)n_in; (void)out_size;

    lstm_r13_kernel<<<B_TOT / NB, 32>>>(x, Wih, Whh, bih, bhh, Wd, bd,
                                        (float*)d_out);
}

// round 14
// speedup vs baseline: 1.5859x; 1.0039x over previous
#include <cuda_runtime.h>

// LSTM: B=4096, T=512, I=10, H=32, O=1. Gate order i,f,g,o.
// R14 = R13 (MUFU.TANH activations: sigmoid(x)=0.5+0.5*tanh(x/2) with i,f,o
// weights pre-scaled by 0.5; recurrent weights in regs as f32x2 j-pairs,
// even/odd-j halves in u64 halves, k-inner interleave, x-weights in smem,
// bias peeled into q=0 fma2) + R10's mixed grid: 544 NB=4 blocks + 640 NB=3
// blocks = 1184 = 148*8 -> one wave at 8 blocks/SM (2.0 warps/SMSP).
// With the tanh-shortened activation window, the extra resident warp can now
// convert to fma-pipe throughput (rt=3 bank-limited floor = ~495us).

#define B_TOT 4096
#define T_LEN 512
#define I_DIM 10
#define H_DIM 32
#define XSTRIDE (T_LEN * I_DIM)   // 5120
#define NB4_BLOCKS 544
#define NB3_BLOCKS 640
#define GRID_SZ (NB4_BLOCKS + NB3_BLOCKS)   // 1184 = 148*8

#define SH (0.5f)   // pre-scale for sigmoid gates (i, f, o)

typedef unsigned long long u64;

__device__ __forceinline__ u64 fma2(u64 a, u64 b, u64 c) {
    u64 d;
    asm("fma.rn.f32x2 %0, %1, %2, %3;" : "=l"(d) : "l"(a), "l"(b), "l"(c));
    return d;
}
__device__ __forceinline__ u64 pack2(float lo, float hi) {
    u64 d;
    asm("mov.b64 %0, {%1, %2};" : "=l"(d) : "f"(lo), "f"(hi));
    return d;
}
__device__ __forceinline__ void unpack2(u64 v, float& lo, float& hi) {
    asm("mov.b64 {%0, %1}, %2;" : "=f"(lo), "=f"(hi) : "l"(v));
}
__device__ __forceinline__ float tanhm(float x) {
    float y; asm("tanh.approx.f32 %0, %1;" : "=f"(y) : "f"(x)); return y;
}
// Pre-scaled sigmoid: input already = x/2. sig(x) = 0.5 + 0.5*tanh(x/2).
__device__ __forceinline__ float sig_half(float y) {
    return fmaf(0.5f, tanhm(y), 0.5f);
}

template<int NBk>
__device__ __forceinline__ void lstm_run(
    int lane, int b0,
    const u64 (&whi)[16], const u64 (&whf)[16],
    const u64 (&whg)[16], const u64 (&who)[16],
    u64 bp_i, u64 bp_f, u64 bp_g, u64 bp_o,
    const ulonglong2 (*sWx_if)[32], const ulonglong2 (*sWx_go)[32],
    float (*sH)[H_DIM], float (*sX)[12],
    const float* __restrict__ x,
    const float* __restrict__ Wd, const float* __restrict__ bd,
    float* __restrict__ out)
{
    float h[NBk], c[NBk], xv[NBk];
#pragma unroll
    for (int k = 0; k < NBk; k++) { h[k] = 0.0f; c[k] = 0.0f; xv[k] = 0.0f; }

    const float* xb = x + b0 * XSTRIDE + lane;
    if (lane < I_DIM) {
#pragma unroll
        for (int k = 0; k < NBk; k++) xv[k] = xb[k * XSTRIDE];   // x(0)
    }
    int toff = I_DIM;   // element offset of x(t+1)

    for (int t = 0; t < T_LEN; t++) {
        // Publish compact h and x.
#pragma unroll
        for (int k = 0; k < NBk; k++) sH[k][lane] = h[k];
        if (lane < I_DIM) {
#pragma unroll
            for (int k = 0; k < NBk; k++) sX[k][lane] = xv[k];
        }
        __syncwarp();

        // Prefetch next timestep's x (clamped; overlaps gate compute).
        if (lane < I_DIM) {
#pragma unroll
            for (int k = 0; k < NBk; k++) xv[k] = xb[k * XSTRIDE + toff];
        }
        toff = min(toff + I_DIM, XSTRIDE - I_DIM);

        u64 ai[NBk], af[NBk], ag[NBk], ao[NBk];
        // q = 0 peeled: bias enters via the fma2 addend.
#pragma unroll
        for (int k = 0; k < NBk; k++) {
            const ulonglong2 hp = *(const ulonglong2*)&sH[k][0];
            ai[k] = fma2(whi[0], hp.x, bp_i);
            af[k] = fma2(whf[0], hp.x, bp_f);
            ag[k] = fma2(whg[0], hp.x, bp_g);
            ao[k] = fma2(who[0], hp.x, bp_o);
            ai[k] = fma2(whi[1], hp.y, ai[k]);
            af[k] = fma2(whf[1], hp.y, af[k]);
            ag[k] = fma2(whg[1], hp.y, ag[k]);
            ao[k] = fma2(who[1], hp.y, ao[k]);
        }
#pragma unroll
        for (int q = 1; q < 8; q++) {
#pragma unroll
            for (int k = 0; k < NBk; k++) {
                const ulonglong2 hp = *(const ulonglong2*)&sH[k][4 * q];
                ai[k] = fma2(whi[2 * q],     hp.x, ai[k]);
                af[k] = fma2(whf[2 * q],     hp.x, af[k]);
                ag[k] = fma2(whg[2 * q],     hp.x, ag[k]);
                ao[k] = fma2(who[2 * q],     hp.x, ao[k]);
                ai[k] = fma2(whi[2 * q + 1], hp.y, ai[k]);
                af[k] = fma2(whf[2 * q + 1], hp.y, af[k]);
                ag[k] = fma2(whg[2 * q + 1], hp.y, ag[k]);
                ao[k] = fma2(who[2 * q + 1], hp.y, ao[k]);
            }
        }
        // Input part: p-outer so only 4 weight u64s live at a time.
#pragma unroll
        for (int p = 0; p < 5; p++) {
            const ulonglong2 wif = sWx_if[p][lane];
            const ulonglong2 wgo = sWx_go[p][lane];
#pragma unroll
            for (int k = 0; k < NBk; k++) {
                const u64 xq = *(const u64*)&sX[k][2 * p];
                ai[k] = fma2(wif.x, xq, ai[k]);
                af[k] = fma2(wif.y, xq, af[k]);
                ag[k] = fma2(wgo.x, xq, ag[k]);
                ao[k] = fma2(wgo.y, xq, ao[k]);
            }
        }

        // Activations via MUFU.TANH + state update.
#pragma unroll
        for (int k = 0; k < NBk; k++) {
            float lo, hi;
            unpack2(ag[k], lo, hi); const float gg = tanhm(lo + hi);
            unpack2(af[k], lo, hi); const float gf = sig_half(lo + hi);
            unpack2(ai[k], lo, hi); const float gi = sig_half(lo + hi);
            unpack2(ao[k], lo, hi); const float go = sig_half(lo + hi);
            c[k] = fmaf(gf, c[k], gi * gg);
            h[k] = go * tanhm(c[k]);
        }
        __syncwarp();
    }

    // Final dense: out[b] = sum_l h[b][l] * Wd[l] + bd
    const float wd = Wd[lane];
    const float bdv = bd[0];
#pragma unroll
    for (int k = 0; k < NBk; k++) {
        float p = h[k] * wd;
#pragma unroll
        for (int off = 16; off; off >>= 1)
            p += __shfl_xor_sync(0xffffffffu, p, off);
        if (lane == 0) out[b0 + k] = p + bdv;
    }
}

__global__ __launch_bounds__(32, 8) void lstm_r14_kernel(
    const float* __restrict__ x,    // [B, T, I]
    const float* __restrict__ Wih,  // [4H, I]
    const float* __restrict__ Whh,  // [4H, H]
    const float* __restrict__ bih,  // [4H]
    const float* __restrict__ bhh,  // [4H]
    const float* __restrict__ Wd,   // [1, H]
    const float* __restrict__ bd,   // [1]
    float* __restrict__ out)        // [B, 1]
{
    __shared__ ulonglong2 sWx_if[5][32];   // pre-scaled x-weights
    __shared__ ulonglong2 sWx_go[5][32];
    __shared__ __align__(16) float sH[4][H_DIM];
    __shared__ __align__(16) float sX[4][12];

    const int lane = threadIdx.x;
    const int bid = blockIdx.x;

    // ---- Recurrent weights into registers (paired over j).
    // i,f,o rows scaled by 0.5 (sigmoid-via-tanh); g row unscaled.
    u64 whi[16], whf[16], whg[16], who[16];
#pragma unroll
    for (int p = 0; p < 16; p++) {
        const float* r0 = &Whh[(0 * 32 + lane) * H_DIM + 2 * p];
        const float* r1 = &Whh[(1 * 32 + lane) * H_DIM + 2 * p];
        const float* r2 = &Whh[(2 * 32 + lane) * H_DIM + 2 * p];
        const float* r3 = &Whh[(3 * 32 + lane) * H_DIM + 2 * p];
        whi[p] = pack2(SH * r0[0], SH * r0[1]);
        whf[p] = pack2(SH * r1[0], SH * r1[1]);
        whg[p] = pack2(r2[0], r2[1]);
        who[p] = pack2(SH * r3[0], SH * r3[1]);
    }
    // x-weights into smem, same scaling, packed per gate-pair.
#pragma unroll
    for (int p = 0; p < 5; p++) {
        ulonglong2 v;
        v.x = pack2(SH * Wih[(0 * 32 + lane) * I_DIM + 2 * p],
                    SH * Wih[(0 * 32 + lane) * I_DIM + 2 * p + 1]);
        v.y = pack2(SH * Wih[(1 * 32 + lane) * I_DIM + 2 * p],
                    SH * Wih[(1 * 32 + lane) * I_DIM + 2 * p + 1]);
        sWx_if[p][lane] = v;
        v.x = pack2(Wih[(2 * 32 + lane) * I_DIM + 2 * p],
                    Wih[(2 * 32 + lane) * I_DIM + 2 * p + 1]);
        v.y = pack2(SH * Wih[(3 * 32 + lane) * I_DIM + 2 * p],
                    SH * Wih[(3 * 32 + lane) * I_DIM + 2 * p + 1]);
        sWx_go[p][lane] = v;
    }
    // Scaled bias packed (bias, 0) for the q=0 peeled fma2.
    const u64 bp_i = pack2(SH * (bih[0 * 32 + lane] + bhh[0 * 32 + lane]), 0.0f);
    const u64 bp_f = pack2(SH * (bih[1 * 32 + lane] + bhh[1 * 32 + lane]), 0.0f);
    const u64 bp_g = pack2(bih[2 * 32 + lane] + bhh[2 * 32 + lane], 0.0f);
    const u64 bp_o = pack2(SH * (bih[3 * 32 + lane] + bhh[3 * 32 + lane]), 0.0f);
    __syncwarp();

    if (bid < NB4_BLOCKS) {
        lstm_run<4>(lane, 4 * bid,
                    whi, whf, whg, who, bp_i, bp_f, bp_g, bp_o,
                    sWx_if, sWx_go, sH, sX, x, Wd, bd, out);
    } else {
        lstm_run<3>(lane, NB4_BLOCKS * 4 + 3 * (bid - NB4_BLOCKS),
                    whi, whf, whg, who, bp_i, bp_f, bp_g, bp_o,
                    sWx_if, sWx_go, sH, sX, x, Wd, bd, out);
    }
}

extern "C" void kernel_launch(void* const* d_in, const int* in_sizes, int n_in,
                              void* d_out, int out_size) {
    const float* x   = (const float*)d_in[0];
    const float* Wih = (const float*)d_in[1];
    const float* Whh = (const float*)d_in[2];
    const float* bih = (const float*)d_in[3];
    const float* bhh = (const float*)d_in[4];
    const float* Wd  = (const float*)d_in[5];
    const float* bd  = (const float*)d_in[6];
    (void)in_sizes; (void)n_in; (void)out_size;

    lstm_r14_kernel<<<GRID_SZ, 32>>>(x, Wih, Whh, bih, bhh, Wd, bd,
                                     (float*)d_out);
}

// round 15
// speedup vs baseline: 1.8259x; 1.1514x over previous
#include <cuda_runtime.h>
#include <cuda_fp16.h>

// LSTM: B=4096, T=512, I=10, H=32, O=1. Gate order i,f,g,o.
// R15 = R14 skeleton (mixed 544xNB4 + 640xNB3 = 1184 = 148*8 one-wave grid,
// k-inner interleave, MUFU.TANH activations with sigmoid(x)=0.5+0.5*tanh(x/2)
// folded into 0.5-scaled i/f/o weights) with the gate GEMV in FP16:
//   - weights as __half2 j-pairs in registers (HFMA2: rt=2 vs fma2's rt=3)
//   - h and x published as __half in smem (broadcast LDS volume halved)
//   - accumulate in __half2 (even-j half, odd-j half); fp32 only at activations
//   - bias split-init: acc0 = (f16(b), f16(b - f16(b))) -> lo+hi == b exactly
//   - c, h state remain fp32 in registers
// fma-pipe work/step: 336*rt3 -> 336*rt2 => ~1.35x predicted.

#define B_TOT 4096
#define T_LEN 512
#define I_DIM 10
#define H_DIM 32
#define XSTRIDE (T_LEN * I_DIM)   // 5120
#define NB4_BLOCKS 544
#define NB3_BLOCKS 640
#define GRID_SZ (NB4_BLOCKS + NB3_BLOCKS)   // 1184 = 148*8

#define SH (0.5f)   // pre-scale for sigmoid gates (i, f, o)

typedef unsigned long long u64;

union U16H { uint4 u; __half2 h[4]; };        // 16B <-> 4x half2
union U16L { ulonglong2 u; __half2 h[4]; };   // 16B <-> 4x half2

__device__ __forceinline__ float tanhm(float x) {
    float y; asm("tanh.approx.f32 %0, %1;" : "=f"(y) : "f"(x)); return y;
}
// Pre-scaled sigmoid: input already = x/2. sig(x) = 0.5 + 0.5*tanh(x/2).
__device__ __forceinline__ float sig_half(float y) {
    return fmaf(0.5f, tanhm(y), 0.5f);
}
// Bias split: (f16(b), f16(b - f16(b))) so lo+hi reconstructs b in fp32.
__device__ __forceinline__ __half2 bias_split(float b) {
    const __half hi = __float2half_rn(b);
    const float resid = b - __half2float(hi);
    return __halves2half2(hi, __float2half_rn(resid));
}
__device__ __forceinline__ float hsum2f(__half2 a) {
    const float2 v = __half22float2(a);
    return v.x + v.y;
}

template<int NBk>
__device__ __forceinline__ void lstm_run(
    int lane, int b0,
    const __half2 (&whi)[16], const __half2 (&whf)[16],
    const __half2 (&whg)[16], const __half2 (&who)[16],
    __half2 bp_i, __half2 bp_f, __half2 bp_g, __half2 bp_o,
    const ulonglong2 (*sWx16)[32],
    __half (*sH16)[H_DIM], __half (*sX16)[16],
    const float* __restrict__ x,
    const float* __restrict__ Wd, const float* __restrict__ bd,
    float* __restrict__ out)
{
    float h[NBk], c[NBk], xv[NBk];
#pragma unroll
    for (int k = 0; k < NBk; k++) { h[k] = 0.0f; c[k] = 0.0f; xv[k] = 0.0f; }

    const float* xb = x + b0 * XSTRIDE + lane;
    if (lane < I_DIM) {
#pragma unroll
        for (int k = 0; k < NBk; k++) xv[k] = xb[k * XSTRIDE];   // x(0)
    }
    int toff = I_DIM;   // element offset of x(t+1)

    for (int t = 0; t < T_LEN; t++) {
        // Publish h and x as fp16.
#pragma unroll
        for (int k = 0; k < NBk; k++) sH16[k][lane] = __float2half_rn(h[k]);
        if (lane < I_DIM) {
#pragma unroll
            for (int k = 0; k < NBk; k++) sX16[k][lane] = __float2half_rn(xv[k]);
        }
        __syncwarp();

        // Prefetch next timestep's x (clamped; overlaps gate compute).
        if (lane < I_DIM) {
#pragma unroll
            for (int k = 0; k < NBk; k++) xv[k] = xb[k * XSTRIDE + toff];
        }
        toff = min(toff + I_DIM, XSTRIDE - I_DIM);

        __half2 ai[NBk], af[NBk], ag[NBk], ao[NBk];

        // q = 0 chunk peeled: bias split enters as the HFMA2 addend.
#pragma unroll
        for (int k = 0; k < NBk; k++) {
            U16H r; r.u = *(const uint4*)&sH16[k][0];   // h[0..7] as 4x half2
            ai[k] = __hfma2(whi[0], r.h[0], bp_i);
            af[k] = __hfma2(whf[0], r.h[0], bp_f);
            ag[k] = __hfma2(whg[0], r.h[0], bp_g);
            ao[k] = __hfma2(who[0], r.h[0], bp_o);
#pragma unroll
            for (int j = 1; j < 4; j++) {
                ai[k] = __hfma2(whi[j], r.h[j], ai[k]);
                af[k] = __hfma2(whf[j], r.h[j], af[k]);
                ag[k] = __hfma2(whg[j], r.h[j], ag[k]);
                ao[k] = __hfma2(who[j], r.h[j], ao[k]);
            }
        }
        // Remaining recurrent chunks: q = 1..3 (h[8q .. 8q+7]).
#pragma unroll
        for (int q = 1; q < 4; q++) {
#pragma unroll
            for (int k = 0; k < NBk; k++) {
                U16H r; r.u = *(const uint4*)&sH16[k][8 * q];
#pragma unroll
                for (int j = 0; j < 4; j++) {
                    ai[k] = __hfma2(whi[4 * q + j], r.h[j], ai[k]);
                    af[k] = __hfma2(whf[4 * q + j], r.h[j], af[k]);
                    ag[k] = __hfma2(whg[4 * q + j], r.h[j], ag[k]);
                    ao[k] = __hfma2(who[4 * q + j], r.h[j], ao[k]);
                }
            }
        }
        // Input part: p-outer; one LDS.128 yields all 4 gates' weight pairs.
#pragma unroll
        for (int p = 0; p < 5; p++) {
            U16L w; w.u = sWx16[p][lane];   // h[0]=i, h[1]=f, h[2]=g, h[3]=o
#pragma unroll
            for (int k = 0; k < NBk; k++) {
                const __half2 xq = *(const __half2*)&sX16[k][2 * p];
                ai[k] = __hfma2(w.h[0], xq, ai[k]);
                af[k] = __hfma2(w.h[1], xq, af[k]);
                ag[k] = __hfma2(w.h[2], xq, ag[k]);
                ao[k] = __hfma2(w.h[3], xq, ao[k]);
            }
        }

        // Activations (fp32, MUFU.TANH) + state update.
#pragma unroll
        for (int k = 0; k < NBk; k++) {
            const float gg = tanhm(hsum2f(ag[k]));
            const float gf = sig_half(hsum2f(af[k]));
            const float gi = sig_half(hsum2f(ai[k]));
            const float go = sig_half(hsum2f(ao[k]));
            c[k] = fmaf(gf, c[k], gi * gg);
            h[k] = go * tanhm(c[k]);
        }
        __syncwarp();
    }

    // Final dense (fp32): out[b] = sum_l h[b][l] * Wd[l] + bd
    const float wd = Wd[lane];
    const float bdv = bd[0];
#pragma unroll
    for (int k = 0; k < NBk; k++) {
        float p = h[k] * wd;
#pragma unroll
        for (int off = 16; off; off >>= 1)
            p += __shfl_xor_sync(0xffffffffu, p, off);
        if (lane == 0) out[b0 + k] = p + bdv;
    }
}

__global__ __launch_bounds__(32, 8) void lstm_r15_kernel(
    const float* __restrict__ x,    // [B, T, I]
    const float* __restrict__ Wih,  // [4H, I]
    const float* __restrict__ Whh,  // [4H, H]
    const float* __restrict__ bih,  // [4H]
    const float* __restrict__ bhh,  // [4H]
    const float* __restrict__ Wd,   // [1, H]
    const float* __restrict__ bd,   // [1]
    float* __restrict__ out)        // [B, 1]
{
    __shared__ ulonglong2 sWx16[5][32];                 // fp16 x-weights
    __shared__ __align__(16) __half sH16[4][H_DIM];     // fp16 h broadcast
    __shared__ __align__(16) __half sX16[4][16];        // fp16 x broadcast

    const int lane = threadIdx.x;
    const int bid = blockIdx.x;

    // ---- Recurrent weights into registers as fp16x2 j-pairs.
    // i,f,o rows scaled by 0.5 (sigmoid-via-tanh); g row unscaled.
    __half2 whi[16], whf[16], whg[16], who[16];
#pragma unroll
    for (int p = 0; p < 16; p++) {
        const float* r0 = &Whh[(0 * 32 + lane) * H_DIM + 2 * p];
        const float* r1 = &Whh[(1 * 32 + lane) * H_DIM + 2 * p];
        const float* r2 = &Whh[(2 * 32 + lane) * H_DIM + 2 * p];
        const float* r3 = &Whh[(3 * 32 + lane) * H_DIM + 2 * p];
        whi[p] = __floats2half2_rn(SH * r0[0], SH * r0[1]);
        whf[p] = __floats2half2_rn(SH * r1[0], SH * r1[1]);
        whg[p] = __floats2half2_rn(r2[0], r2[1]);
        who[p] = __floats2half2_rn(SH * r3[0], SH * r3[1]);
    }
    // x-weights into smem: per (p, lane) one 16B = 4 gates' __half2 pairs.
#pragma unroll
    for (int p = 0; p < 5; p++) {
        U16L w;
        w.h[0] = __floats2half2_rn(SH * Wih[(0 * 32 + lane) * I_DIM + 2 * p],
                                   SH * Wih[(0 * 32 + lane) * I_DIM + 2 * p + 1]);
        w.h[1] = __floats2half2_rn(SH * Wih[(1 * 32 + lane) * I_DIM + 2 * p],
                                   SH * Wih[(1 * 32 + lane) * I_DIM + 2 * p + 1]);
        w.h[2] = __floats2half2_rn(Wih[(2 * 32 + lane) * I_DIM + 2 * p],
                                   Wih[(2 * 32 + lane) * I_DIM + 2 * p + 1]);
        w.h[3] = __floats2half2_rn(SH * Wih[(3 * 32 + lane) * I_DIM + 2 * p],
                                   SH * Wih[(3 * 32 + lane) * I_DIM + 2 * p + 1]);
        sWx16[p][lane] = w.u;
    }
    // Bias (scaled for sigmoid gates), split across accumulator halves.
    const __half2 bp_i = bias_split(SH * (bih[0 * 32 + lane] + bhh[0 * 32 + lane]));
    const __half2 bp_f = bias_split(SH * (bih[1 * 32 + lane] + bhh[1 * 32 + lane]));
    const __half2 bp_g = bias_split(bih[2 * 32 + lane] + bhh[2 * 32 + lane]);
    const __half2 bp_o = bias_split(SH * (bih[3 * 32 + lane] + bhh[3 * 32 + lane]));
    __syncwarp();

    if (bid < NB4_BLOCKS) {
        lstm_run<4>(lane, 4 * bid,
                    whi, whf, whg, who, bp_i, bp_f, bp_g, bp_o,
                    sWx16, sH16, sX16, x, Wd, bd, out);
    } else {
        lstm_run<3>(lane, NB4_BLOCKS * 4 + 3 * (bid - NB4_BLOCKS),
                    whi, whf, whg, who, bp_i, bp_f, bp_g, bp_o,
                    sWx16, sH16, sX16, x, Wd, bd, out);
    }
}

extern "C" void kernel_launch(void* const* d_in, const int* in_sizes, int n_in,
                              void* d_out, int out_size) {
    const float* x   = (const float*)d_in[0];
    const float* Wih = (const float*)d_in[1];
    const float* Whh = (const float*)d_in[2];
    const float* bih = (const float*)d_in[3];
    const float* bhh = (const float*)d_in[4];
    const float* Wd  = (const float*)d_in[5];
    const float* bd  = (const float*)d_in[6];
    (void)in_sizes; (void)n_in; (void)out_size;

    lstm_r15_kernel<<<GRID_SZ, 32>>>(x, Wih, Whh, bih, bhh, Wd, bd,
                                     (float*)d_out);
}